// round 1
// baseline (speedup 1.0000x reference)
#include <cuda_runtime.h>
#include <cstddef>

#define BN 2
#define CC 5
#define KK 256
#define NN (512*512)
#define NB 128                 // accumulate blocks per batch
#define LOG2E 1.4426950408889634f

// Scratch (no allocs allowed): centers folded as M = 2*log2e*c, Bv = -log2e*|c|^2
__device__ float g_M[BN][CC][KK];
__device__ float g_Bv[BN][KK];
__device__ float g_partial[BN][NB][6][KK];   // per-block partial sums: slot 0 = wsum, 1..5 = sum pix_c*aff
__device__ float g_acc[BN][6][KK];

__device__ __forceinline__ float ex2f(float x) {
    float y; asm("ex2.approx.ftz.f32 %0, %1;" : "=f"(y) : "f"(x)); return y;
}
__device__ __forceinline__ float rcpf(float x) {
    float y; asm("rcp.approx.ftz.f32 %0, %1;" : "=f"(y) : "f"(x)); return y;
}

// ---------------- init: 32x32 block-mean centers -> M, Bv ----------------
__global__ void init_kernel(const float* __restrict__ x) {
    int k = blockIdx.x, b = blockIdx.y;
    int gy = k >> 4, gx = k & 15;
    const float* base = x + (size_t)b * CC * NN + (size_t)(gy * 32) * 512 + gx * 32;
    int tid = threadIdx.x;
    __shared__ float red[8][CC];

    float s[CC];
#pragma unroll
    for (int c = 0; c < CC; c++) s[c] = 0.f;
#pragma unroll
    for (int i = 0; i < 4; i++) {
        int p = tid + i * 256;
        int rr = p >> 5, cl = p & 31;
#pragma unroll
        for (int c = 0; c < CC; c++)
            s[c] += base[(size_t)c * NN + rr * 512 + cl];
    }
#pragma unroll
    for (int c = 0; c < CC; c++)
#pragma unroll
        for (int d = 16; d; d >>= 1) s[c] += __shfl_xor_sync(~0u, s[c], d);
    int lane = tid & 31, w = tid >> 5;
    if (lane == 0)
#pragma unroll
        for (int c = 0; c < CC; c++) red[w][c] = s[c];
    __syncthreads();
    if (tid == 0) {
        float c2 = 0.f;
#pragma unroll
        for (int c = 0; c < CC; c++) {
            float t = 0.f;
#pragma unroll
            for (int w2 = 0; w2 < 8; w2++) t += red[w2][c];
            float cen = t * (1.0f / 1024.0f);
            c2 = fmaf(cen, cen, c2);
            g_M[b][c][k] = 2.0f * LOG2E * cen;
        }
        g_Bv[b][k] = -LOG2E * c2;
    }
}

// ------------- fused affinity + center accumulation (per iteration) -------------
// Warp-cooperative: each lane owns 8 clusters (k = j*32 + lane). Pixels are
// broadcast through shuffles; softmax over K done via warp reduction;
// accumulators live in registers; deterministic smem tree reduce per block.
__global__ void __launch_bounds__(256) accum_kernel(const float* __restrict__ x) {
    int b = blockIdx.y;
    const float* px = x + (size_t)b * CC * NN;
    int tid = threadIdx.x, lane = tid & 31, warp = tid >> 5;

    float m[8][CC], bb[8];
#pragma unroll
    for (int j = 0; j < 8; j++) {
        int k = j * 32 + lane;
        bb[j] = g_Bv[b][k];
#pragma unroll
        for (int c = 0; c < CC; c++) m[j][c] = g_M[b][c][k];
    }
    float aw[8], as[8][CC];
#pragma unroll
    for (int j = 0; j < 8; j++) {
        aw[j] = 0.f;
#pragma unroll
        for (int c = 0; c < CC; c++) as[j][c] = 0.f;
    }

    const int W = NB * 8;
    for (int n0 = (blockIdx.x * 8 + warp) * 32; n0 < NN; n0 += W * 32) {
        float v[CC];
#pragma unroll
        for (int c = 0; c < CC; c++) v[c] = px[(size_t)c * NN + n0 + lane];
        float up2 = v[0] * v[0];
#pragma unroll
        for (int c = 1; c < CC; c++) up2 = fmaf(v[c], v[c], up2);
        up2 *= LOG2E;

#pragma unroll 2
        for (int s = 0; s < 32; s++) {
            float pp[CC];
#pragma unroll
            for (int c = 0; c < CC; c++) pp[c] = __shfl_sync(~0u, v[c], s);
            float U = __shfl_sync(~0u, up2, s);

            float e[8];
            float lsum = 0.f;
#pragma unroll
            for (int j = 0; j < 8; j++) {
                float sc = fmaf(pp[0], m[j][0], bb[j]);
                sc = fmaf(pp[1], m[j][1], sc);
                sc = fmaf(pp[2], m[j][2], sc);
                sc = fmaf(pp[3], m[j][3], sc);
                sc = fmaf(pp[4], m[j][4], sc);
                e[j] = ex2f(sc - U);
                lsum += e[j];
            }
#pragma unroll
            for (int d = 16; d; d >>= 1) lsum += __shfl_xor_sync(~0u, lsum, d);
            float r = rcpf(lsum);
#pragma unroll
            for (int j = 0; j < 8; j++) {
                float a = e[j] * r;
                aw[j] += a;
#pragma unroll
                for (int c = 0; c < CC; c++)
                    as[j][c] = fmaf(pp[c], a, as[j][c]);
            }
        }
    }

    // deterministic block reduce: each warp stores its 48 values, then fixed-order sum
    __shared__ float sred[8][6 * KK];   // 48 KB
#pragma unroll
    for (int j = 0; j < 8; j++) {
        int k = j * 32 + lane;
        sred[warp][0 * KK + k] = aw[j];
#pragma unroll
        for (int c = 0; c < CC; c++) sred[warp][(1 + c) * KK + k] = as[j][c];
    }
    __syncthreads();
    float* pout = (float*)&g_partial[b][blockIdx.x][0][0];
    for (int i = tid; i < 6 * KK; i += 256) {
        float t = 0.f;
#pragma unroll
        for (int w2 = 0; w2 < 8; w2++) t += sred[w2][i];
        pout[i] = t;
    }
}

// ------------- reduce partials (deterministic) -------------
__global__ void reduce_kernel() {
    int slot = blockIdx.x, b = blockIdx.y;   // grid (6, BN)
    int k = threadIdx.x;
    float s0 = 0.f, s1 = 0.f, s2 = 0.f, s3 = 0.f;
#pragma unroll 1
    for (int i = 0; i < NB; i += 4) {
        s0 += g_partial[b][i + 0][slot][k];
        s1 += g_partial[b][i + 1][slot][k];
        s2 += g_partial[b][i + 2][slot][k];
        s3 += g_partial[b][i + 3][slot][k];
    }
    g_acc[b][slot][k] = (s0 + s1) + (s2 + s3);
}

// ------------- update centers -> M, Bv -------------
__global__ void update_kernel() {
    int b = blockIdx.x, k = threadIdx.x;
    float w = g_acc[b][0][k] + 1e-16f;
    float c2 = 0.f;
#pragma unroll
    for (int c = 0; c < CC; c++) {
        float cen = g_acc[b][1 + c][k] / w;
        c2 = fmaf(cen, cen, c2);
        g_M[b][c][k] = 2.0f * LOG2E * cen;
    }
    g_Bv[b][k] = -LOG2E * c2;
}

// ------------- final affinity, write out [B, K, N] -------------
// Thread handles 4 consecutive pixels; two passes over K (recompute scores);
// float4 coalesced stores; centers in smem (warp-broadcast reads).
__global__ void __launch_bounds__(256) final_kernel(const float* __restrict__ x,
                                                    float* __restrict__ out) {
    int b = blockIdx.y;
    __shared__ float sM[CC][KK];
    __shared__ float sB[KK];
    for (int i = threadIdx.x; i < CC * KK; i += 256)
        ((float*)sM)[i] = ((const float*)g_M[b])[i];
    sB[threadIdx.x] = g_Bv[b][threadIdx.x];
    __syncthreads();

    int n0 = (blockIdx.x * 256 + threadIdx.x) * 4;
    const float* px = x + (size_t)b * CC * NN;

    float4 v[CC];
    float U0 = 0.f, U1 = 0.f, U2 = 0.f, U3 = 0.f;
#pragma unroll
    for (int c = 0; c < CC; c++) {
        v[c] = *(const float4*)(px + (size_t)c * NN + n0);
        U0 = fmaf(v[c].x, v[c].x, U0);
        U1 = fmaf(v[c].y, v[c].y, U1);
        U2 = fmaf(v[c].z, v[c].z, U2);
        U3 = fmaf(v[c].w, v[c].w, U3);
    }
    U0 *= LOG2E; U1 *= LOG2E; U2 *= LOG2E; U3 *= LOG2E;

    float sm0 = 0.f, sm1 = 0.f, sm2 = 0.f, sm3 = 0.f;
#pragma unroll 8
    for (int k = 0; k < KK; k++) {
        float bk = sB[k];
        float a0 = bk, a1 = bk, a2 = bk, a3 = bk;
#pragma unroll
        for (int c = 0; c < CC; c++) {
            float mk = sM[c][k];
            a0 = fmaf(v[c].x, mk, a0);
            a1 = fmaf(v[c].y, mk, a1);
            a2 = fmaf(v[c].z, mk, a2);
            a3 = fmaf(v[c].w, mk, a3);
        }
        sm0 += ex2f(a0 - U0);
        sm1 += ex2f(a1 - U1);
        sm2 += ex2f(a2 - U2);
        sm3 += ex2f(a3 - U3);
    }
    float r0 = rcpf(sm0), r1 = rcpf(sm1), r2 = rcpf(sm2), r3 = rcpf(sm3);

    float* ob = out + (size_t)b * KK * NN + n0;
#pragma unroll 8
    for (int k = 0; k < KK; k++) {
        float bk = sB[k];
        float a0 = bk, a1 = bk, a2 = bk, a3 = bk;
#pragma unroll
        for (int c = 0; c < CC; c++) {
            float mk = sM[c][k];
            a0 = fmaf(v[c].x, mk, a0);
            a1 = fmaf(v[c].y, mk, a1);
            a2 = fmaf(v[c].z, mk, a2);
            a3 = fmaf(v[c].w, mk, a3);
        }
        float4 o;
        o.x = ex2f(a0 - U0) * r0;
        o.y = ex2f(a1 - U1) * r1;
        o.z = ex2f(a2 - U2) * r2;
        o.w = ex2f(a3 - U3) * r3;
        *(float4*)(ob + (size_t)k * NN) = o;
    }
}

extern "C" void kernel_launch(void* const* d_in, const int* in_sizes, int n_in,
                              void* d_out, int out_size) {
    const float* x = (const float*)d_in[0];
    float* out = (float*)d_out;
    (void)in_sizes; (void)n_in; (void)out_size;  // nspix=256, n_iter=10 fixed by problem

    init_kernel<<<dim3(KK, BN), 256>>>(x);
    for (int it = 0; it < 10; it++) {
        accum_kernel<<<dim3(NB, BN), 256>>>(x);
        reduce_kernel<<<dim3(6, BN), 256>>>();
        update_kernel<<<BN, 256>>>();
    }
    final_kernel<<<dim3(NN / 1024, BN), 256>>>(x, out);
}